// round 13
// baseline (speedup 1.0000x reference)
#include <cuda_runtime.h>
#include <cuda_fp16.h>
#include <cstdint>

// ---------------------------------------------------------------------------
// Problem constants
// ---------------------------------------------------------------------------
#define IN_F    4096
#define OUT_F   16384
#define ACT_IN  2048
#define ACT_OUT 8192
#define NROWS   8192      // B*S

// GEMM tiling: CTA 256(M) x 128(N), 8 warps as 4(M) x 2(N), warp tile 64x64
#define BM 256
#define BN 128
#define KC 64                    // K elements per stage (128 B/row in smem)
#define NSTAGE (ACT_IN / KC)     // 32
#define NTH 256
#define NBUF 4                   // cp.async pipeline depth

// SMEM per stage: A 32K | B 16K = 48 KB; 4 stages = 192 KB
#define T_A 0
#define T_B 32768
#define STAGE_BYTES 49152
#define SMEM_TOTAL  (NBUF * STAGE_BYTES)   // 196608

// Epilogue staging: C tile [BM][SC_PITCH] fp32, padded pitch vs bank conflicts
#define SC_PITCH 132              // 256*132*4 = 135168 <= SMEM_TOTAL

// fp16 operand scratch (allocation-free rule: __device__ globals).
// Both operands rounded once to fp16; measured rel_err ~3e-4 << 1e-3 gate.
__device__ __half g_A[(size_t)NROWS * ACT_IN];
__device__ __half g_B[(size_t)ACT_OUT * ACT_IN];
// Inverse output map: g_inv[c] = n+1 if out_idx[n]==c else 0.
__device__ int g_inv[OUT_F];

// ---------------------------------------------------------------------------
// PTX helpers (sm_80-baseline only — harness lowers through plain compute_103)
// ---------------------------------------------------------------------------
__device__ __forceinline__ uint32_t smem_u32(const void* p) {
    uint32_t a;
    asm("{ .reg .u64 t; cvta.to.shared.u64 t, %1; cvt.u32.u64 %0, t; }"
        : "=r"(a) : "l"(p));
    return a;
}

#define SWZ(o) ((o) ^ (((o) >> 3) & 0x70))   // SW128 xor swizzle (16B granules)

#define CPA16(sa, gp) \
    asm volatile("cp.async.cg.shared.global [%0], [%1], 16;" :: "r"(sa), "l"(gp) : "memory")
#define CPA_COMMIT() asm volatile("cp.async.commit_group;" ::: "memory")
#define CPA_WAIT(n)  asm volatile("cp.async.wait_group %0;" :: "n"(n) : "memory")

#define LDSM4(r0, r1, r2, r3, a) \
    asm volatile("ldmatrix.sync.aligned.m8n8.x4.shared.b16 {%0,%1,%2,%3}, [%4];" \
                 : "=r"(r0), "=r"(r1), "=r"(r2), "=r"(r3) : "r"(a))

// D += A*B, fp16 in, fp32 accum.  A frag 4xb32, B frag 2xb32, C 4xf32.
#define MMA(c, a0, a1, a2, a3, b0, b1) \
    asm volatile("mma.sync.aligned.m16n8k16.row.col.f32.f16.f16.f32 " \
                 "{%0,%1,%2,%3}, {%4,%5,%6,%7}, {%8,%9}, {%0,%1,%2,%3};" \
                 : "+f"((c)[0]), "+f"((c)[1]), "+f"((c)[2]), "+f"((c)[3]) \
                 : "r"(a0), "r"(a1), "r"(a2), "r"(a3), "r"(b0), "r"(b1))

// ---------------------------------------------------------------------------
// Pre-pass 1: gather active input cols, round fp32 -> fp16 (no zero-fill:
// the GEMM epilogue writes every output element exactly once).
// ---------------------------------------------------------------------------
__global__ void nsl_gather_x(const float* __restrict__ x,
                             const int* __restrict__ in_idx) {
    const int k = blockIdx.x * blockDim.x + threadIdx.x;
    const int m = blockIdx.y;
    const int c = __ldg(&in_idx[k]);
    g_A[(size_t)m * ACT_IN + k] = __float2half_rn(__ldg(&x[(size_t)m * IN_F + c]));
}

// Pre-pass 2: round weight fp32 -> fp16
__global__ void nsl_round_w(const float* __restrict__ w) {
    const size_t i = blockIdx.x * (size_t)blockDim.x + threadIdx.x;
    g_B[i] = __float2half_rn(__ldg(&w[i]));
}

// Pre-pass 3: inverse output-column map
__global__ void nsl_inv_clear() {
    g_inv[blockIdx.x * blockDim.x + threadIdx.x] = 0;
}
__global__ void nsl_inv_set(const int* __restrict__ out_idx) {
    const int n = blockIdx.x * blockDim.x + threadIdx.x;
    g_inv[__ldg(&out_idx[n])] = n + 1;
}

// ---------------------------------------------------------------------------
// Main GEMM: single fp16 HMMA product, fp32 register accumulation, 4-stage
// cp.async pipeline, SWP'd LDSM rotation. Epilogue writes the CTA's DENSE
// output-column stripe [stripe_start, stripe_end) — computed values at active
// columns, zeros elsewhere — fully coalesced, no separate zero pass.
// (out_idx sorted => stripes partition [0, OUT_F).)
// ---------------------------------------------------------------------------
__global__ __launch_bounds__(NTH, 1)
void nsl_mma(const float* __restrict__ bias,
             const int*   __restrict__ out_idx,
             float*       __restrict__ out) {
    extern __shared__ __align__(1024) char smem[];
    const uint32_t sb = smem_u32(smem);
    const int tid  = threadIdx.x;
    const int wid  = tid >> 5;
    const int lane = tid & 31;
    const int m0 = blockIdx.y * BM;
    const int n0 = blockIdx.x * BN;

    const int warp_m = wid >> 1;       // 0..3  -> 64-row slab of M
    const int warp_n = wid & 1;        // 0..1  -> 64-col slab of N

    // ---- cp.async slot mapping ----
    int aG[8]; uint32_t aS[8];
    int bG[4]; uint32_t bS[4];
#pragma unroll
    for (int i = 0; i < 8; i++) {
        const int id = tid + i * NTH;
        const int r = id >> 3, cv = id & 7;
        aG[i] = r * ACT_IN + cv * 8;
        aS[i] = SWZ((uint32_t)(r * 128 + cv * 16));
    }
#pragma unroll
    for (int i = 0; i < 4; i++) {
        const int id = tid + i * NTH;
        const int r = id >> 3, cv = id & 7;
        bG[i] = r * ACT_IN + cv * 8;
        bS[i] = SWZ((uint32_t)(r * 128 + cv * 16));
    }
    const __half* pA = g_A + (size_t)m0 * ACT_IN;
    const __half* pB = g_B + (size_t)n0 * ACT_IN;

    auto load_stage = [&](int s) {
        const uint32_t base = sb + (s & (NBUF - 1)) * STAGE_BYTES;
        const int ke = s * KC;
#pragma unroll
        for (int i = 0; i < 8; i++)
            CPA16(base + T_A + aS[i], pA + ke + aG[i]);
#pragma unroll
        for (int i = 0; i < 4; i++)
            CPA16(base + T_B + bS[i], pB + ke + bG[i]);
        CPA_COMMIT();
    };

    // ---- ldmatrix lane addressing ----
    const int lrow  = lane & 15;
    const uint32_t lkoff = (uint32_t)((lane >> 4) * 16);

    uint32_t aBase[4];
#pragma unroll
    for (int mt = 0; mt < 4; mt++) {
        const int row = warp_m * 64 + mt * 16 + lrow;
        aBase[mt] = (uint32_t)(row * 128) + (((uint32_t)(row & 7)) << 4);
    }
    uint32_t bBase[4];
#pragma unroll
    for (int g = 0; g < 4; g++) {
        const int row = warp_n * 64 + g * 16 + lrow;
        bBase[g] = (uint32_t)(row * 128) + (((uint32_t)(row & 7)) << 4);
    }

    // ---- accumulators: 4 m-tiles x 8 n8-tiles x 4 f32 = 128 regs ----
    float acc[4][8][4];
#pragma unroll
    for (int i = 0; i < 4; i++)
#pragma unroll
        for (int j = 0; j < 8; j++)
#pragma unroll
            for (int q = 0; q < 4; q++) acc[i][j][q] = 0.0f;

    uint32_t aF[2][4][4];
    uint32_t bF[2][4];

    // ---- prologue: 3 stages in flight ----
    load_stage(0);
    load_stage(1);
    load_stage(2);

    for (int s = 0; s < NSTAGE; s++) {
        CPA_WAIT(2);
        __syncthreads();

        if (s + 3 < NSTAGE) load_stage(s + 3);

        const uint32_t base = sb + (s & (NBUF - 1)) * STAGE_BYTES;

        // stage preamble: first A-quad + first B group
#pragma unroll
        for (int mt = 0; mt < 4; mt++)
            LDSM4(aF[0][mt][0], aF[0][mt][1], aF[0][mt][2], aF[0][mt][3],
                  base + T_A + (aBase[mt] ^ lkoff));
        LDSM4(bF[0][0], bF[0][1], bF[0][2], bF[0][3],
              base + T_B + (bBase[0] ^ lkoff));

#pragma unroll
        for (int ks = 0; ks < 4; ks++) {
            const uint32_t kb  = (uint32_t)(ks * 32) + lkoff;
            const uint32_t kbn = (uint32_t)((ks + 1) * 32) + lkoff;
            const int kc = ks & 1;

#pragma unroll
            for (int g = 0; g < 4; g++) {
                if (g < 3) {
                    LDSM4(bF[(g + 1) & 1][0], bF[(g + 1) & 1][1],
                          bF[(g + 1) & 1][2], bF[(g + 1) & 1][3],
                          base + T_B + (bBase[g + 1] ^ kb));
                } else if (ks < 3) {
#pragma unroll
                    for (int mt = 0; mt < 4; mt++)
                        LDSM4(aF[kc ^ 1][mt][0], aF[kc ^ 1][mt][1],
                              aF[kc ^ 1][mt][2], aF[kc ^ 1][mt][3],
                              base + T_A + (aBase[mt] ^ kbn));
                    LDSM4(bF[0][0], bF[0][1], bF[0][2], bF[0][3],
                          base + T_B + (bBase[0] ^ kbn));
                }

                const int gb = g & 1;
#pragma unroll
                for (int mt = 0; mt < 4; mt++) {
                    MMA(acc[mt][2*g+0], aF[kc][mt][0], aF[kc][mt][1],
                        aF[kc][mt][2], aF[kc][mt][3], bF[gb][0], bF[gb][2]);
                    MMA(acc[mt][2*g+1], aF[kc][mt][0], aF[kc][mt][1],
                        aF[kc][mt][2], aF[kc][mt][3], bF[gb][1], bF[gb][3]);
                }
            }
        }
    }

    // ---- epilogue part 1: stage C (+bias) into smem, pitch-padded ----
    __syncthreads();                   // everyone done reading pipeline smem
    float* sC = (float*)smem;          // [BM][SC_PITCH]

    const int trow = lane >> 2;
    const int tcol = (lane & 3) * 2;
    float bv0[8], bv1[8];
#pragma unroll
    for (int nt = 0; nt < 8; nt++) {
        const int n = n0 + warp_n * 64 + nt * 8 + tcol;
        bv0[nt] = __ldg(&bias[n]);
        bv1[nt] = __ldg(&bias[n + 1]);
    }
#pragma unroll
    for (int mt = 0; mt < 4; mt++) {
        const int r0 = warp_m * 64 + mt * 16 + trow;
        const int r1 = r0 + 8;
#pragma unroll
        for (int nt = 0; nt < 8; nt++) {
            const int c0 = warp_n * 64 + nt * 8 + tcol;
            sC[r0 * SC_PITCH + c0]     = acc[mt][nt][0] + bv0[nt];
            sC[r0 * SC_PITCH + c0 + 1] = acc[mt][nt][1] + bv1[nt];
            sC[r1 * SC_PITCH + c0]     = acc[mt][nt][2] + bv0[nt];
            sC[r1 * SC_PITCH + c0 + 1] = acc[mt][nt][3] + bv1[nt];
        }
    }
    __syncthreads();

    // ---- epilogue part 2: dense stripe sweep (coalesced, zeros included) ----
    const int cStart = (blockIdx.x == 0) ? 0 : __ldg(&out_idx[n0]);
    const int cEnd   = (blockIdx.x == gridDim.x - 1) ? OUT_F
                                                     : __ldg(&out_idx[n0 + BN]);
    // per-thread column slots (stripe width ~256, <=512 with overwhelming prob;
    // generic tail loop guards the impossible-but-safe case)
    const int cA = cStart + tid;
    const int cB = cA + NTH;
    const bool hasA = cA < cEnd;
    const bool hasB = cB < cEnd;
    const int nlA = hasA ? (__ldg(&g_inv[cA]) - 1 - n0) : -1;  // <0 -> inactive
    const int nlB = hasB ? (__ldg(&g_inv[cB]) - 1 - n0) : -1;

    for (int r = 0; r < BM; r++) {
        float* orow = out + (size_t)(m0 + r) * OUT_F;
        const float* srow = sC + r * SC_PITCH;
        if (hasA) orow[cA] = (nlA >= 0) ? srow[nlA] : 0.0f;
        if (hasB) orow[cB] = (nlB >= 0) ? srow[nlB] : 0.0f;
        for (int c = cStart + 2 * NTH + tid; c < cEnd; c += NTH) {
            const int nl = __ldg(&g_inv[c]) - 1 - n0;
            orow[c] = (nl >= 0) ? srow[nl] : 0.0f;
        }
    }
}

// ---------------------------------------------------------------------------
// Launch
// ---------------------------------------------------------------------------
extern "C" void kernel_launch(void* const* d_in, const int* in_sizes, int n_in,
                              void* d_out, int out_size) {
    const float* x       = (const float*)d_in[0];
    const float* weight  = (const float*)d_in[1];
    const float* bias    = (const float*)d_in[2];
    const int*   in_idx  = (const int*)d_in[3];
    const int*   out_idx = (const int*)d_in[4];
    float* out = (float*)d_out;

    // pre-pass: gather+round A, round B, inverse output map
    {
        dim3 g(ACT_IN / 256, NROWS);
        nsl_gather_x<<<g, 256>>>(x, in_idx);
    }
    nsl_round_w<<<(ACT_OUT * ACT_IN) / 256, 256>>>(weight);
    nsl_inv_clear<<<OUT_F / 256, 256>>>();
    nsl_inv_set<<<ACT_OUT / 256, 256>>>(out_idx);

    // tensor-core GEMM (mma.sync) + bias + dense-stripe epilogue
    cudaFuncSetAttribute(nsl_mma, cudaFuncAttributeMaxDynamicSharedMemorySize,
                         SMEM_TOTAL);
    dim3 grid(ACT_OUT / BN, NROWS / BM);   // 64 x 32
    nsl_mma<<<grid, NTH, SMEM_TOTAL>>>(bias, out_idx, out);
}

// round 14
// speedup vs baseline: 1.3472x; 1.3472x over previous
#include <cuda_runtime.h>
#include <cuda_fp16.h>
#include <cstdint>

// ---------------------------------------------------------------------------
// Problem constants
// ---------------------------------------------------------------------------
#define IN_F    4096
#define OUT_F   16384
#define ACT_IN  2048
#define ACT_OUT 8192
#define NROWS   8192      // B*S

// GEMM tiling: CTA 256(M) x 128(N), 8 warps as 4(M) x 2(N), warp tile 64x64
#define BM 256
#define BN 128
#define KC 64                    // K elements per stage (128 B/row in smem)
#define NSTAGE (ACT_IN / KC)     // 32
#define NTH 256
#define NBUF 4                   // cp.async pipeline depth

// SMEM per stage: A 32K | B 16K = 48 KB; 4 stages = 192 KB
#define T_A 0
#define T_B 32768
#define STAGE_BYTES 49152
#define SMEM_TOTAL  (NBUF * STAGE_BYTES)   // 196608

// Epilogue staging: C tile [BM][SC_PITCH] fp32 (135 KB <= SMEM_TOTAL)
#define SC_PITCH 132

// fp16 operand scratch (allocation-free rule: __device__ globals).
__device__ __half g_A[(size_t)NROWS * ACT_IN];
__device__ __half g_B[(size_t)ACT_OUT * ACT_IN];
// Inverse output map: g_inv[c] = n+1 if out_idx[n]==c else 0.
__device__ int g_inv[OUT_F];

// ---------------------------------------------------------------------------
// PTX helpers (sm_80-baseline only — harness lowers through plain compute_103)
// ---------------------------------------------------------------------------
__device__ __forceinline__ uint32_t smem_u32(const void* p) {
    uint32_t a;
    asm("{ .reg .u64 t; cvta.to.shared.u64 t, %1; cvt.u32.u64 %0, t; }"
        : "=r"(a) : "l"(p));
    return a;
}

#define SWZ(o) ((o) ^ (((o) >> 3) & 0x70))   // SW128 xor swizzle (16B granules)

#define CPA16(sa, gp) \
    asm volatile("cp.async.cg.shared.global [%0], [%1], 16;" :: "r"(sa), "l"(gp) : "memory")
#define CPA_COMMIT() asm volatile("cp.async.commit_group;" ::: "memory")
#define CPA_WAIT(n)  asm volatile("cp.async.wait_group %0;" :: "n"(n) : "memory")

#define LDSM4(r0, r1, r2, r3, a) \
    asm volatile("ldmatrix.sync.aligned.m8n8.x4.shared.b16 {%0,%1,%2,%3}, [%4];" \
                 : "=r"(r0), "=r"(r1), "=r"(r2), "=r"(r3) : "r"(a))

// D += A*B, fp16 in, fp32 accum.  A frag 4xb32, B frag 2xb32, C 4xf32.
#define MMA(c, a0, a1, a2, a3, b0, b1) \
    asm volatile("mma.sync.aligned.m16n8k16.row.col.f32.f16.f16.f32 " \
                 "{%0,%1,%2,%3}, {%4,%5,%6,%7}, {%8,%9}, {%0,%1,%2,%3};" \
                 : "+f"((c)[0]), "+f"((c)[1]), "+f"((c)[2]), "+f"((c)[3]) \
                 : "r"(a0), "r"(a1), "r"(a2), "r"(a3), "r"(b0), "r"(b1))

// ---------------------------------------------------------------------------
// Pre-pass 1 (fused): gather+round A, round W.  Same index space:
// NROWS*ACT_IN == ACT_OUT*ACT_IN, so thread (m,k) handles both.
// No output zero-fill — the GEMM epilogue writes every element exactly once.
// ---------------------------------------------------------------------------
__global__ void nsl_prep(const float* __restrict__ x,
                         const float* __restrict__ w,
                         const int* __restrict__ in_idx) {
    const int k = blockIdx.x * blockDim.x + threadIdx.x;
    const int m = blockIdx.y;
    const int c = __ldg(&in_idx[k]);
    const size_t i = (size_t)m * ACT_IN + k;
    g_A[i] = __float2half_rn(__ldg(&x[(size_t)m * IN_F + c]));
    g_B[i] = __float2half_rn(__ldg(&w[i]));
}

// Pre-pass 2: inverse output-column map
__global__ void nsl_inv_clear() {
    g_inv[blockIdx.x * blockDim.x + threadIdx.x] = 0;
}
__global__ void nsl_inv_set(const int* __restrict__ out_idx) {
    const int n = blockIdx.x * blockDim.x + threadIdx.x;
    g_inv[__ldg(&out_idx[n])] = n + 1;
}

// ---------------------------------------------------------------------------
// Main GEMM: single fp16 HMMA product, fp32 register accumulation, 4-stage
// cp.async pipeline, SWP'd LDSM rotation. Dense-stripe epilogue v2:
// column-major sweep, 8-row latency-batched, conflict-free.
// ---------------------------------------------------------------------------
__global__ __launch_bounds__(NTH, 1)
void nsl_mma(const float* __restrict__ bias,
             const int*   __restrict__ out_idx,
             float*       __restrict__ out) {
    extern __shared__ __align__(1024) char smem[];
    const uint32_t sb = smem_u32(smem);
    const int tid  = threadIdx.x;
    const int wid  = tid >> 5;
    const int lane = tid & 31;
    const int m0 = blockIdx.y * BM;
    const int n0 = blockIdx.x * BN;

    const int warp_m = wid >> 1;       // 0..3  -> 64-row slab of M
    const int warp_n = wid & 1;        // 0..1  -> 64-col slab of N

    // ---- cp.async slot mapping ----
    int aG[8]; uint32_t aS[8];
    int bG[4]; uint32_t bS[4];
#pragma unroll
    for (int i = 0; i < 8; i++) {
        const int id = tid + i * NTH;
        const int r = id >> 3, cv = id & 7;
        aG[i] = r * ACT_IN + cv * 8;
        aS[i] = SWZ((uint32_t)(r * 128 + cv * 16));
    }
#pragma unroll
    for (int i = 0; i < 4; i++) {
        const int id = tid + i * NTH;
        const int r = id >> 3, cv = id & 7;
        bG[i] = r * ACT_IN + cv * 8;
        bS[i] = SWZ((uint32_t)(r * 128 + cv * 16));
    }
    const __half* pA = g_A + (size_t)m0 * ACT_IN;
    const __half* pB = g_B + (size_t)n0 * ACT_IN;

    auto load_stage = [&](int s) {
        const uint32_t base = sb + (s & (NBUF - 1)) * STAGE_BYTES;
        const int ke = s * KC;
#pragma unroll
        for (int i = 0; i < 8; i++)
            CPA16(base + T_A + aS[i], pA + ke + aG[i]);
#pragma unroll
        for (int i = 0; i < 4; i++)
            CPA16(base + T_B + bS[i], pB + ke + bG[i]);
        CPA_COMMIT();
    };

    // ---- ldmatrix lane addressing ----
    const int lrow  = lane & 15;
    const uint32_t lkoff = (uint32_t)((lane >> 4) * 16);

    uint32_t aBase[4];
#pragma unroll
    for (int mt = 0; mt < 4; mt++) {
        const int row = warp_m * 64 + mt * 16 + lrow;
        aBase[mt] = (uint32_t)(row * 128) + (((uint32_t)(row & 7)) << 4);
    }
    uint32_t bBase[4];
#pragma unroll
    for (int g = 0; g < 4; g++) {
        const int row = warp_n * 64 + g * 16 + lrow;
        bBase[g] = (uint32_t)(row * 128) + (((uint32_t)(row & 7)) << 4);
    }

    // ---- accumulators: 4 m-tiles x 8 n8-tiles x 4 f32 = 128 regs ----
    float acc[4][8][4];
#pragma unroll
    for (int i = 0; i < 4; i++)
#pragma unroll
        for (int j = 0; j < 8; j++)
#pragma unroll
            for (int q = 0; q < 4; q++) acc[i][j][q] = 0.0f;

    uint32_t aF[2][4][4];
    uint32_t bF[2][4];

    // ---- prologue: 3 stages in flight ----
    load_stage(0);
    load_stage(1);
    load_stage(2);

    for (int s = 0; s < NSTAGE; s++) {
        CPA_WAIT(2);
        __syncthreads();

        if (s + 3 < NSTAGE) load_stage(s + 3);

        const uint32_t base = sb + (s & (NBUF - 1)) * STAGE_BYTES;

        // stage preamble: first A-quad + first B group
#pragma unroll
        for (int mt = 0; mt < 4; mt++)
            LDSM4(aF[0][mt][0], aF[0][mt][1], aF[0][mt][2], aF[0][mt][3],
                  base + T_A + (aBase[mt] ^ lkoff));
        LDSM4(bF[0][0], bF[0][1], bF[0][2], bF[0][3],
              base + T_B + (bBase[0] ^ lkoff));

#pragma unroll
        for (int ks = 0; ks < 4; ks++) {
            const uint32_t kb  = (uint32_t)(ks * 32) + lkoff;
            const uint32_t kbn = (uint32_t)((ks + 1) * 32) + lkoff;
            const int kc = ks & 1;

#pragma unroll
            for (int g = 0; g < 4; g++) {
                if (g < 3) {
                    LDSM4(bF[(g + 1) & 1][0], bF[(g + 1) & 1][1],
                          bF[(g + 1) & 1][2], bF[(g + 1) & 1][3],
                          base + T_B + (bBase[g + 1] ^ kb));
                } else if (ks < 3) {
#pragma unroll
                    for (int mt = 0; mt < 4; mt++)
                        LDSM4(aF[kc ^ 1][mt][0], aF[kc ^ 1][mt][1],
                              aF[kc ^ 1][mt][2], aF[kc ^ 1][mt][3],
                              base + T_A + (aBase[mt] ^ kbn));
                    LDSM4(bF[0][0], bF[0][1], bF[0][2], bF[0][3],
                          base + T_B + (bBase[0] ^ kbn));
                }

                const int gb = g & 1;
#pragma unroll
                for (int mt = 0; mt < 4; mt++) {
                    MMA(acc[mt][2*g+0], aF[kc][mt][0], aF[kc][mt][1],
                        aF[kc][mt][2], aF[kc][mt][3], bF[gb][0], bF[gb][2]);
                    MMA(acc[mt][2*g+1], aF[kc][mt][0], aF[kc][mt][1],
                        aF[kc][mt][2], aF[kc][mt][3], bF[gb][1], bF[gb][3]);
                }
            }
        }
    }

    // ---- epilogue part 1: stage C (+bias) into smem, pitch-padded ----
    __syncthreads();                   // everyone done reading pipeline smem
    float* sC = (float*)smem;          // [BM][SC_PITCH]

    const int trow = lane >> 2;
    const int tcol = (lane & 3) * 2;
    float bv0[8], bv1[8];
#pragma unroll
    for (int nt = 0; nt < 8; nt++) {
        const int n = n0 + warp_n * 64 + nt * 8 + tcol;
        bv0[nt] = __ldg(&bias[n]);
        bv1[nt] = __ldg(&bias[n + 1]);
    }
#pragma unroll
    for (int mt = 0; mt < 4; mt++) {
        const int r0 = warp_m * 64 + mt * 16 + trow;
        const int r1 = r0 + 8;
#pragma unroll
        for (int nt = 0; nt < 8; nt++) {
            const int c0 = warp_n * 64 + nt * 8 + tcol;
            sC[r0 * SC_PITCH + c0]     = acc[mt][nt][0] + bv0[nt];
            sC[r0 * SC_PITCH + c0 + 1] = acc[mt][nt][1] + bv1[nt];
            sC[r1 * SC_PITCH + c0]     = acc[mt][nt][2] + bv0[nt];
            sC[r1 * SC_PITCH + c0 + 1] = acc[mt][nt][3] + bv1[nt];
        }
    }
    __syncthreads();

    // ---- epilogue part 2: dense stripe sweep, column-major, 8-row batches ----
    // Each thread owns output column(s) c; active -> copy sC column nl,
    // inactive -> zeros. LDS batched x8 for latency; stores coalesced.
    const int cStart = (blockIdx.x == 0) ? 0 : __ldg(&out_idx[n0]);
    const int cEnd   = (blockIdx.x == gridDim.x - 1) ? OUT_F
                                                     : __ldg(&out_idx[n0 + BN]);
    for (int c = cStart + tid; c < cEnd; c += NTH) {
        const int nl  = __ldg(&g_inv[c]) - 1 - n0;   // <0 -> inactive
        const bool act = (nl >= 0);
        const float* scol = sC + (act ? nl : 0);     // always-valid address
        float* ocol = out + (size_t)m0 * OUT_F + c;
#pragma unroll 1
        for (int r8 = 0; r8 < BM; r8 += 8) {
            float v[8];
#pragma unroll
            for (int i = 0; i < 8; i++)
                v[i] = scol[(r8 + i) * SC_PITCH];
#pragma unroll
            for (int i = 0; i < 8; i++)
                ocol[(size_t)(r8 + i) * OUT_F] = act ? v[i] : 0.0f;
        }
    }
}

// ---------------------------------------------------------------------------
// Launch
// ---------------------------------------------------------------------------
extern "C" void kernel_launch(void* const* d_in, const int* in_sizes, int n_in,
                              void* d_out, int out_size) {
    const float* x       = (const float*)d_in[0];
    const float* weight  = (const float*)d_in[1];
    const float* bias    = (const float*)d_in[2];
    const int*   in_idx  = (const int*)d_in[3];
    const int*   out_idx = (const int*)d_in[4];
    float* out = (float*)d_out;

    // pre-pass: fused gather+round A / round W, inverse output map
    {
        dim3 g(ACT_IN / 256, NROWS);
        nsl_prep<<<g, 256>>>(x, weight, in_idx);
    }
    nsl_inv_clear<<<OUT_F / 256, 256>>>();
    nsl_inv_set<<<ACT_OUT / 256, 256>>>(out_idx);

    // tensor-core GEMM (mma.sync) + bias + dense-stripe epilogue
    cudaFuncSetAttribute(nsl_mma, cudaFuncAttributeMaxDynamicSharedMemorySize,
                         SMEM_TOTAL);
    dim3 grid(ACT_OUT / BN, NROWS / BM);   // 64 x 32
    nsl_mma<<<grid, NTH, SMEM_TOTAL>>>(bias, out_idx, out);
}

// round 15
// speedup vs baseline: 1.3605x; 1.0098x over previous
#include <cuda_runtime.h>
#include <cuda_fp16.h>
#include <cstdint>

// ---------------------------------------------------------------------------
// Problem constants
// ---------------------------------------------------------------------------
#define IN_F    4096
#define OUT_F   16384
#define ACT_IN  2048
#define ACT_OUT 8192
#define NROWS   8192      // B*S

// GEMM tiling: CTA 256(M) x 128(N), 8 warps as 4(M) x 2(N), warp tile 64x64
#define BM 256
#define BN 128
#define KC 128                   // K elements per stage (2 x 64-col panels)
#define NSTAGE (ACT_IN / KC)     // 16
#define NTH 256
#define NBUF 2                   // double-buffered stages

// SMEM per stage: A panels 2x32K | B panels 2x16K = 96 KB; 2 stages = 192 KB
#define T_A 0                    // A panel p at T_A + p*32768
#define T_B 65536                // B panel p at T_B + p*16384
#define STAGE_BYTES 98304
#define SMEM_TOTAL  (NBUF * STAGE_BYTES)   // 196608

// Epilogue staging: C tile [BM][SC_PITCH] fp32 (135 KB <= SMEM_TOTAL)
#define SC_PITCH 132

// fp16 operand scratch (allocation-free rule: __device__ globals).
__device__ __half g_A[(size_t)NROWS * ACT_IN];
__device__ __half g_B[(size_t)ACT_OUT * ACT_IN];
// Inverse output map: g_inv[c] = n+1 if out_idx[n]==c else 0.
__device__ int g_inv[OUT_F];

// ---------------------------------------------------------------------------
// PTX helpers (sm_80-baseline only — harness lowers through plain compute_103)
// ---------------------------------------------------------------------------
__device__ __forceinline__ uint32_t smem_u32(const void* p) {
    uint32_t a;
    asm("{ .reg .u64 t; cvta.to.shared.u64 t, %1; cvt.u32.u64 %0, t; }"
        : "=r"(a) : "l"(p));
    return a;
}

#define SWZ(o) ((o) ^ (((o) >> 3) & 0x70))   // SW128 xor swizzle (16B granules)

#define CPA16(sa, gp) \
    asm volatile("cp.async.cg.shared.global [%0], [%1], 16;" :: "r"(sa), "l"(gp) : "memory")
#define CPA_COMMIT() asm volatile("cp.async.commit_group;" ::: "memory")
#define CPA_WAIT(n)  asm volatile("cp.async.wait_group %0;" :: "n"(n) : "memory")

#define LDSM4(r0, r1, r2, r3, a) \
    asm volatile("ldmatrix.sync.aligned.m8n8.x4.shared.b16 {%0,%1,%2,%3}, [%4];" \
                 : "=r"(r0), "=r"(r1), "=r"(r2), "=r"(r3) : "r"(a))

// D += A*B, fp16 in, fp32 accum.  A frag 4xb32, B frag 2xb32, C 4xf32.
#define MMA(c, a0, a1, a2, a3, b0, b1) \
    asm volatile("mma.sync.aligned.m16n8k16.row.col.f32.f16.f16.f32 " \
                 "{%0,%1,%2,%3}, {%4,%5,%6,%7}, {%8,%9}, {%0,%1,%2,%3};" \
                 : "+f"((c)[0]), "+f"((c)[1]), "+f"((c)[2]), "+f"((c)[3]) \
                 : "r"(a0), "r"(a1), "r"(a2), "r"(a3), "r"(b0), "r"(b1))

// ---------------------------------------------------------------------------
// Pre-pass 1 (fused): gather+round A, round W (same index space).
// No output zero-fill — the GEMM epilogue writes every element exactly once.
// ---------------------------------------------------------------------------
__global__ void nsl_prep(const float* __restrict__ x,
                         const float* __restrict__ w,
                         const int* __restrict__ in_idx) {
    const int k = blockIdx.x * blockDim.x + threadIdx.x;
    const int m = blockIdx.y;
    const int c = __ldg(&in_idx[k]);
    const size_t i = (size_t)m * ACT_IN + k;
    g_A[i] = __float2half_rn(__ldg(&x[(size_t)m * IN_F + c]));
    g_B[i] = __float2half_rn(__ldg(&w[i]));
}

// Pre-pass 2: inverse output-column map
__global__ void nsl_inv_clear() {
    g_inv[blockIdx.x * blockDim.x + threadIdx.x] = 0;
}
__global__ void nsl_inv_set(const int* __restrict__ out_idx) {
    const int n = blockIdx.x * blockDim.x + threadIdx.x;
    g_inv[__ldg(&out_idx[n])] = n + 1;
}

// ---------------------------------------------------------------------------
// Main GEMM: single fp16 HMMA product, fp32 register accumulation.
// KC=128 double-buffered stages (1 barrier + 1 wait per 8 k16 steps),
// SWP'd LDSM rotation, dense-stripe epilogue.
// ---------------------------------------------------------------------------
__global__ __launch_bounds__(NTH, 1)
void nsl_mma(const float* __restrict__ bias,
             const int*   __restrict__ out_idx,
             float*       __restrict__ out) {
    extern __shared__ __align__(1024) char smem[];
    const uint32_t sb = smem_u32(smem);
    const int tid  = threadIdx.x;
    const int wid  = tid >> 5;
    const int lane = tid & 31;
    const int m0 = blockIdx.y * BM;
    const int n0 = blockIdx.x * BN;

    const int warp_m = wid >> 1;       // 0..3  -> 64-row slab of M
    const int warp_n = wid & 1;        // 0..1  -> 64-col slab of N

    // ---- cp.async slot mapping (per 64-col panel; panel p adds +p*64 k) ----
    int aG[8]; uint32_t aS[8];
    int bG[4]; uint32_t bS[4];
#pragma unroll
    for (int i = 0; i < 8; i++) {
        const int id = tid + i * NTH;
        const int r = id >> 3, cv = id & 7;
        aG[i] = r * ACT_IN + cv * 8;
        aS[i] = SWZ((uint32_t)(r * 128 + cv * 16));
    }
#pragma unroll
    for (int i = 0; i < 4; i++) {
        const int id = tid + i * NTH;
        const int r = id >> 3, cv = id & 7;
        bG[i] = r * ACT_IN + cv * 8;
        bS[i] = SWZ((uint32_t)(r * 128 + cv * 16));
    }
    const __half* pA = g_A + (size_t)m0 * ACT_IN;
    const __half* pB = g_B + (size_t)n0 * ACT_IN;

    auto load_stage = [&](int s) {
        const uint32_t base = sb + (s & (NBUF - 1)) * STAGE_BYTES;
        const int ke = s * KC;
#pragma unroll
        for (int p = 0; p < 2; p++)
#pragma unroll
            for (int i = 0; i < 8; i++)
                CPA16(base + T_A + p * 32768 + aS[i], pA + ke + p * 64 + aG[i]);
#pragma unroll
        for (int p = 0; p < 2; p++)
#pragma unroll
            for (int i = 0; i < 4; i++)
                CPA16(base + T_B + p * 16384 + bS[i], pB + ke + p * 64 + bG[i]);
        CPA_COMMIT();
    };

    // ---- ldmatrix lane addressing (within a panel) ----
    const int lrow  = lane & 15;
    const uint32_t lkoff = (uint32_t)((lane >> 4) * 16);

    uint32_t aBase[4];
#pragma unroll
    for (int mt = 0; mt < 4; mt++) {
        const int row = warp_m * 64 + mt * 16 + lrow;
        aBase[mt] = (uint32_t)(row * 128) + (((uint32_t)(row & 7)) << 4);
    }
    uint32_t bBase[4];
#pragma unroll
    for (int g = 0; g < 4; g++) {
        const int row = warp_n * 64 + g * 16 + lrow;
        bBase[g] = (uint32_t)(row * 128) + (((uint32_t)(row & 7)) << 4);
    }

    // ---- accumulators: 4 m-tiles x 8 n8-tiles x 4 f32 = 128 regs ----
    float acc[4][8][4];
#pragma unroll
    for (int i = 0; i < 4; i++)
#pragma unroll
        for (int j = 0; j < 8; j++)
#pragma unroll
            for (int q = 0; q < 4; q++) acc[i][j][q] = 0.0f;

    uint32_t aF[2][4][4];
    uint32_t bF[2][4];

    // ---- prologue: stage 0 in flight ----
    load_stage(0);

    for (int s = 0; s < NSTAGE; s++) {
        CPA_WAIT(0);          // stage s data resident
        __syncthreads();      // all warps done computing stage s-1
        if (s + 1 < NSTAGE) load_stage(s + 1);   // refills the other buffer

        const uint32_t base = sb + (s & (NBUF - 1)) * STAGE_BYTES;

        // stage preamble: first A-quad + first B group (panel 0)
#pragma unroll
        for (int mt = 0; mt < 4; mt++)
            LDSM4(aF[0][mt][0], aF[0][mt][1], aF[0][mt][2], aF[0][mt][3],
                  base + T_A + (aBase[mt] ^ lkoff));
        LDSM4(bF[0][0], bF[0][1], bF[0][2], bF[0][3],
              base + T_B + (bBase[0] ^ lkoff));

#pragma unroll
        for (int ks = 0; ks < 8; ks++) {
            const uint32_t aPan  = (uint32_t)((ks >> 2) * 32768);
            const uint32_t bPan  = (uint32_t)((ks >> 2) * 16384);
            const uint32_t aPanN = (uint32_t)(((ks + 1) >> 2) * 32768);
            const uint32_t bPanN = (uint32_t)(((ks + 1) >> 2) * 16384);
            const uint32_t kb  = (uint32_t)((ks & 3) * 32) + lkoff;
            const uint32_t kbn = (uint32_t)(((ks + 1) & 3) * 32) + lkoff;
            const int kc = ks & 1;

#pragma unroll
            for (int g = 0; g < 4; g++) {
                if (g < 3) {
                    LDSM4(bF[(g + 1) & 1][0], bF[(g + 1) & 1][1],
                          bF[(g + 1) & 1][2], bF[(g + 1) & 1][3],
                          base + T_B + bPan + (bBase[g + 1] ^ kb));
                } else if (ks < 7) {
#pragma unroll
                    for (int mt = 0; mt < 4; mt++)
                        LDSM4(aF[kc ^ 1][mt][0], aF[kc ^ 1][mt][1],
                              aF[kc ^ 1][mt][2], aF[kc ^ 1][mt][3],
                              base + T_A + aPanN + (aBase[mt] ^ kbn));
                    LDSM4(bF[0][0], bF[0][1], bF[0][2], bF[0][3],
                          base + T_B + bPanN + (bBase[0] ^ kbn));
                }

                const int gb = g & 1;
#pragma unroll
                for (int mt = 0; mt < 4; mt++) {
                    MMA(acc[mt][2*g+0], aF[kc][mt][0], aF[kc][mt][1],
                        aF[kc][mt][2], aF[kc][mt][3], bF[gb][0], bF[gb][2]);
                    MMA(acc[mt][2*g+1], aF[kc][mt][0], aF[kc][mt][1],
                        aF[kc][mt][2], aF[kc][mt][3], bF[gb][1], bF[gb][3]);
                }
            }
        }
    }

    // ---- epilogue part 1: stage C (+bias) into smem, pitch-padded ----
    __syncthreads();                   // everyone done reading pipeline smem
    float* sC = (float*)smem;          // [BM][SC_PITCH]

    const int trow = lane >> 2;
    const int tcol = (lane & 3) * 2;
    float bv0[8], bv1[8];
#pragma unroll
    for (int nt = 0; nt < 8; nt++) {
        const int n = n0 + warp_n * 64 + nt * 8 + tcol;
        bv0[nt] = __ldg(&bias[n]);
        bv1[nt] = __ldg(&bias[n + 1]);
    }
#pragma unroll
    for (int mt = 0; mt < 4; mt++) {
        const int r0 = warp_m * 64 + mt * 16 + trow;
        const int r1 = r0 + 8;
#pragma unroll
        for (int nt = 0; nt < 8; nt++) {
            const int c0 = warp_n * 64 + nt * 8 + tcol;
            sC[r0 * SC_PITCH + c0]     = acc[mt][nt][0] + bv0[nt];
            sC[r0 * SC_PITCH + c0 + 1] = acc[mt][nt][1] + bv1[nt];
            sC[r1 * SC_PITCH + c0]     = acc[mt][nt][2] + bv0[nt];
            sC[r1 * SC_PITCH + c0 + 1] = acc[mt][nt][3] + bv1[nt];
        }
    }
    __syncthreads();

    // ---- epilogue part 2: dense stripe sweep, column-major, 8-row batches ----
    const int cStart = (blockIdx.x == 0) ? 0 : __ldg(&out_idx[n0]);
    const int cEnd   = (blockIdx.x == gridDim.x - 1) ? OUT_F
                                                     : __ldg(&out_idx[n0 + BN]);
    for (int c = cStart + tid; c < cEnd; c += NTH) {
        const int nl  = __ldg(&g_inv[c]) - 1 - n0;   // <0 -> inactive
        const bool act = (nl >= 0);
        const float* scol = sC + (act ? nl : 0);     // always-valid address
        float* ocol = out + (size_t)m0 * OUT_F + c;
#pragma unroll 1
        for (int r8 = 0; r8 < BM; r8 += 8) {
            float v[8];
#pragma unroll
            for (int i = 0; i < 8; i++)
                v[i] = scol[(r8 + i) * SC_PITCH];
#pragma unroll
            for (int i = 0; i < 8; i++)
                ocol[(size_t)(r8 + i) * OUT_F] = act ? v[i] : 0.0f;
        }
    }
}

// ---------------------------------------------------------------------------
// Launch
// ---------------------------------------------------------------------------
extern "C" void kernel_launch(void* const* d_in, const int* in_sizes, int n_in,
                              void* d_out, int out_size) {
    const float* x       = (const float*)d_in[0];
    const float* weight  = (const float*)d_in[1];
    const float* bias    = (const float*)d_in[2];
    const int*   in_idx  = (const int*)d_in[3];
    const int*   out_idx = (const int*)d_in[4];
    float* out = (float*)d_out;

    // pre-pass: fused gather+round A / round W, inverse output map
    {
        dim3 g(ACT_IN / 256, NROWS);
        nsl_prep<<<g, 256>>>(x, weight, in_idx);
    }
    nsl_inv_clear<<<OUT_F / 256, 256>>>();
    nsl_inv_set<<<ACT_OUT / 256, 256>>>(out_idx);

    // tensor-core GEMM (mma.sync) + bias + dense-stripe epilogue
    cudaFuncSetAttribute(nsl_mma, cudaFuncAttributeMaxDynamicSharedMemorySize,
                         SMEM_TOTAL);
    dim3 grid(ACT_OUT / BN, NROWS / BM);   // 64 x 32
    nsl_mma<<<grid, NTH, SMEM_TOTAL>>>(bias, out_idx, out);
}